// round 1
// baseline (speedup 1.0000x reference)
#include <cuda_runtime.h>

// Problem constants
#define B_   4
#define L_   2048
#define D_   1024
#define H_   16
#define DK_  64
#define M_   (B_*L_)      // 8192 rows for projection GEMMs

static const long long OUT_ELEMS  = (long long)B_ * L_ * D_;        // 8388608
static const long long ATTN_ELEMS = (long long)B_ * H_ * L_ * L_;   // 268435456

// Scratch (allocation-free requirement -> __device__ globals)
__device__ float g_Q[(size_t)M_ * D_];
__device__ float g_K[(size_t)M_ * D_];
__device__ float g_V[(size_t)M_ * D_];
__device__ float g_ctx[(size_t)M_ * D_];
// Fallback attn buffer if the harness's d_out only holds `out`
__device__ float g_attn[(size_t)B_ * H_ * L_ * L_];

// ---------------------------------------------------------------------------
// Generic GEMM + bias: C[M,N] = A[M,K] @ W[K,N] + bias[N]
// BM=BN=64, BK=16, 256 threads, 4x4 register tile per thread.
// ---------------------------------------------------------------------------
__global__ __launch_bounds__(256) void gemm_bias_kernel(
    const float* __restrict__ A, const float* __restrict__ W,
    const float* __restrict__ bias, float* __restrict__ C,
    int Mtot, int N, int K)
{
    __shared__ float As[16][64];   // [k][m]
    __shared__ float Ws[16][64];   // [k][n]

    int tid = threadIdx.x;
    int tx = tid & 15, ty = tid >> 4;
    int m0 = blockIdx.y * 64, n0 = blockIdx.x * 64;

    int arow = tid >> 2;           // 0..63
    int acol = (tid & 3) * 4;      // 0,4,8,12
    int wrow = tid >> 4;           // 0..15
    int wcol = (tid & 15) * 4;     // 0..60

    float acc[4][4];
#pragma unroll
    for (int i = 0; i < 4; i++)
#pragma unroll
        for (int j = 0; j < 4; j++) acc[i][j] = 0.f;

    for (int k0 = 0; k0 < K; k0 += 16) {
        float4 av = *(const float4*)(A + (size_t)(m0 + arow) * K + k0 + acol);
        As[acol + 0][arow] = av.x;
        As[acol + 1][arow] = av.y;
        As[acol + 2][arow] = av.z;
        As[acol + 3][arow] = av.w;
        float4 wv = *(const float4*)(W + (size_t)(k0 + wrow) * N + n0 + wcol);
        *(float4*)&Ws[wrow][wcol] = wv;
        __syncthreads();
#pragma unroll
        for (int k = 0; k < 16; k++) {
            float4 a = *(const float4*)&As[k][ty * 4];
            float4 w = *(const float4*)&Ws[k][tx * 4];
            float ar[4] = {a.x, a.y, a.z, a.w};
            float wr[4] = {w.x, w.y, w.z, w.w};
#pragma unroll
            for (int i = 0; i < 4; i++)
#pragma unroll
                for (int j = 0; j < 4; j++)
                    acc[i][j] += ar[i] * wr[j];
        }
        __syncthreads();
    }

    float4 bv = *(const float4*)(bias + n0 + tx * 4);
    float br[4] = {bv.x, bv.y, bv.z, bv.w};
#pragma unroll
    for (int i = 0; i < 4; i++) {
        int m = m0 + ty * 4 + i;
        float4 o;
        o.x = acc[i][0] + br[0];
        o.y = acc[i][1] + br[1];
        o.z = acc[i][2] + br[2];
        o.w = acc[i][3] + br[3];
        *(float4*)(C + (size_t)m * N + n0 + tx * 4) = o;
    }
}

// ---------------------------------------------------------------------------
// scores[bh, q, k] = scale * dot(Q[b,q,h,:], K[b,k,h,:])   (64x64 tile/block)
// Q/K stored as [B, L, H*DK] -> head h slice has row stride D_.
// ---------------------------------------------------------------------------
__global__ __launch_bounds__(256) void scores_kernel(
    const float* __restrict__ Q, const float* __restrict__ Kb,
    float* __restrict__ attn, float scale)
{
    int bh = blockIdx.z;
    int b = bh >> 4, h = bh & 15;
    int q0 = blockIdx.y * 64, k0 = blockIdx.x * 64;

    __shared__ float Qs[64][65];   // [q][d], padded
    __shared__ float Ks[64][65];   // [k][d], padded

    int tid = threadIdx.x;
    int tx = tid & 15, ty = tid >> 4;
    int lrow = tid >> 4;           // 0..15
    int lcol = (tid & 15) * 4;     // 0..60

    const float* Qbase = Q + ((size_t)b * L_ + q0) * D_ + h * DK_;
    const float* Kbase = Kb + ((size_t)b * L_ + k0) * D_ + h * DK_;

#pragma unroll
    for (int r = 0; r < 64; r += 16) {
        float4 qv = *(const float4*)(Qbase + (size_t)(r + lrow) * D_ + lcol);
        Qs[r + lrow][lcol + 0] = qv.x;
        Qs[r + lrow][lcol + 1] = qv.y;
        Qs[r + lrow][lcol + 2] = qv.z;
        Qs[r + lrow][lcol + 3] = qv.w;
        float4 kv = *(const float4*)(Kbase + (size_t)(r + lrow) * D_ + lcol);
        Ks[r + lrow][lcol + 0] = kv.x;
        Ks[r + lrow][lcol + 1] = kv.y;
        Ks[r + lrow][lcol + 2] = kv.z;
        Ks[r + lrow][lcol + 3] = kv.w;
    }
    __syncthreads();

    float acc[4][4];
#pragma unroll
    for (int i = 0; i < 4; i++)
#pragma unroll
        for (int j = 0; j < 4; j++) acc[i][j] = 0.f;

#pragma unroll 16
    for (int d = 0; d < 64; d++) {
        float ar[4], br[4];
#pragma unroll
        for (int i = 0; i < 4; i++) ar[i] = Qs[ty * 4 + i][d];
#pragma unroll
        for (int j = 0; j < 4; j++) br[j] = Ks[tx * 4 + j][d];
#pragma unroll
        for (int i = 0; i < 4; i++)
#pragma unroll
            for (int j = 0; j < 4; j++)
                acc[i][j] += ar[i] * br[j];
    }

#pragma unroll
    for (int i = 0; i < 4; i++) {
        size_t row = (size_t)bh * L_ + q0 + ty * 4 + i;
        float4 o;
        o.x = acc[i][0] * scale;
        o.y = acc[i][1] * scale;
        o.z = acc[i][2] * scale;
        o.w = acc[i][3] * scale;
        *(float4*)(attn + row * L_ + k0 + tx * 4) = o;
    }
}

// ---------------------------------------------------------------------------
// In-place row softmax over last dim (L_=2048). One block (256 thr) per row.
// ---------------------------------------------------------------------------
__global__ __launch_bounds__(256) void softmax_kernel(float* __restrict__ attn)
{
    __shared__ float red_max[8];
    __shared__ float red_sum[8];

    size_t row = (size_t)blockIdx.y * (size_t)gridDim.x + blockIdx.x;
    float* p = attn + row * (size_t)L_;
    int tid = threadIdx.x;

    float4 a = *(float4*)(p + tid * 8);
    float4 b = *(float4*)(p + tid * 8 + 4);

    float m = fmaxf(fmaxf(fmaxf(a.x, a.y), fmaxf(a.z, a.w)),
                    fmaxf(fmaxf(b.x, b.y), fmaxf(b.z, b.w)));
#pragma unroll
    for (int o = 16; o > 0; o >>= 1)
        m = fmaxf(m, __shfl_xor_sync(0xFFFFFFFFu, m, o));
    if ((tid & 31) == 0) red_max[tid >> 5] = m;
    __syncthreads();
    float mall = red_max[0];
#pragma unroll
    for (int i = 1; i < 8; i++) mall = fmaxf(mall, red_max[i]);

    a.x = __expf(a.x - mall); a.y = __expf(a.y - mall);
    a.z = __expf(a.z - mall); a.w = __expf(a.w - mall);
    b.x = __expf(b.x - mall); b.y = __expf(b.y - mall);
    b.z = __expf(b.z - mall); b.w = __expf(b.w - mall);

    float s = a.x + a.y + a.z + a.w + b.x + b.y + b.z + b.w;
#pragma unroll
    for (int o = 16; o > 0; o >>= 1)
        s += __shfl_xor_sync(0xFFFFFFFFu, s, o);
    if ((tid & 31) == 0) red_sum[tid >> 5] = s;
    __syncthreads();
    float sall = 0.f;
#pragma unroll
    for (int i = 0; i < 8; i++) sall += red_sum[i];

    float inv = 1.0f / sall;
    a.x *= inv; a.y *= inv; a.z *= inv; a.w *= inv;
    b.x *= inv; b.y *= inv; b.z *= inv; b.w *= inv;
    *(float4*)(p + tid * 8) = a;
    *(float4*)(p + tid * 8 + 4) = b;
}

// ---------------------------------------------------------------------------
// ctx[b, l, h*DK+d] = sum_k attn[bh, l, k] * V[b, k, h*DK+d]
// Block: 64 l-rows x 64 (=DK) cols for one (b,h). Loop over k in 64-tiles.
// ---------------------------------------------------------------------------
__global__ __launch_bounds__(256) void ctx_kernel(
    const float* __restrict__ attn, const float* __restrict__ V,
    float* __restrict__ ctx)
{
    int bh = blockIdx.y;
    int b = bh >> 4, h = bh & 15;
    int l0 = blockIdx.x * 64;

    __shared__ float As[64][65];   // attn tile [l][k]
    __shared__ float Vs[64][65];   // V tile    [k][d]

    int tid = threadIdx.x;
    int tx = tid & 15, ty = tid >> 4;
    int lrow = tid >> 4;           // 0..15
    int lcol = (tid & 15) * 4;     // 0..60

    const float* Abase = attn + ((size_t)bh * L_ + l0) * L_;
    const float* Vbase = V + (size_t)b * L_ * D_ + h * DK_;

    float acc[4][4];
#pragma unroll
    for (int i = 0; i < 4; i++)
#pragma unroll
        for (int j = 0; j < 4; j++) acc[i][j] = 0.f;

    for (int k0 = 0; k0 < L_; k0 += 64) {
#pragma unroll
        for (int r = 0; r < 64; r += 16) {
            float4 av = *(const float4*)(Abase + (size_t)(r + lrow) * L_ + k0 + lcol);
            As[r + lrow][lcol + 0] = av.x;
            As[r + lrow][lcol + 1] = av.y;
            As[r + lrow][lcol + 2] = av.z;
            As[r + lrow][lcol + 3] = av.w;
            float4 vv = *(const float4*)(Vbase + (size_t)(k0 + r + lrow) * D_ + lcol);
            Vs[r + lrow][lcol + 0] = vv.x;
            Vs[r + lrow][lcol + 1] = vv.y;
            Vs[r + lrow][lcol + 2] = vv.z;
            Vs[r + lrow][lcol + 3] = vv.w;
        }
        __syncthreads();
#pragma unroll 8
        for (int k = 0; k < 64; k++) {
            float ar[4], vr[4];
#pragma unroll
            for (int i = 0; i < 4; i++) ar[i] = As[ty * 4 + i][k];
#pragma unroll
            for (int j = 0; j < 4; j++) vr[j] = Vs[k][tx * 4 + j];
#pragma unroll
            for (int i = 0; i < 4; i++)
#pragma unroll
                for (int j = 0; j < 4; j++)
                    acc[i][j] += ar[i] * vr[j];
        }
        __syncthreads();
    }

#pragma unroll
    for (int i = 0; i < 4; i++) {
        size_t orow = (size_t)b * L_ + l0 + ty * 4 + i;
        float4 o;
        o.x = acc[i][0]; o.y = acc[i][1]; o.z = acc[i][2]; o.w = acc[i][3];
        *(float4*)(ctx + orow * D_ + h * DK_ + tx * 4) = o;
    }
}

// ---------------------------------------------------------------------------
extern "C" void kernel_launch(void* const* d_in, const int* in_sizes, int n_in,
                              void* d_out, int out_size)
{
    const float* query = (const float*)d_in[0];
    const float* key_  = (const float*)d_in[1];
    const float* value = (const float*)d_in[2];
    const float* Wq    = (const float*)d_in[3];
    const float* bq    = (const float*)d_in[4];
    const float* Wk    = (const float*)d_in[5];
    const float* bk    = (const float*)d_in[6];
    const float* Wv    = (const float*)d_in[7];
    const float* bv    = (const float*)d_in[8];
    const float* Wo    = (const float*)d_in[9];
    const float* bo    = (const float*)d_in[10];

    float* out = (float*)d_out;

    // attn destination: second output region if present, else device scratch
    float* attn_ptr = nullptr;
    if ((long long)out_size >= OUT_ELEMS + ATTN_ELEMS) {
        attn_ptr = out + OUT_ELEMS;
    } else {
        cudaGetSymbolAddress((void**)&attn_ptr, g_attn);
    }

    float* Qbuf; cudaGetSymbolAddress((void**)&Qbuf, g_Q);
    float* Kbuf; cudaGetSymbolAddress((void**)&Kbuf, g_K);
    float* Vbuf; cudaGetSymbolAddress((void**)&Vbuf, g_V);
    float* Cbuf; cudaGetSymbolAddress((void**)&Cbuf, g_ctx);

    dim3 gemm_grid(D_ / 64, M_ / 64);   // (16, 128)
    gemm_bias_kernel<<<gemm_grid, 256>>>(query, Wq, bq, Qbuf, M_, D_, D_);
    gemm_bias_kernel<<<gemm_grid, 256>>>(key_,  Wk, bk, Kbuf, M_, D_, D_);
    gemm_bias_kernel<<<gemm_grid, 256>>>(value, Wv, bv, Vbuf, M_, D_, D_);

    const float scale = 0.125f;   // 1/sqrt(64)
    dim3 sc_grid(L_ / 64, L_ / 64, B_ * H_);   // (32, 32, 64)
    scores_kernel<<<sc_grid, 256>>>(Qbuf, Kbuf, attn_ptr, scale);

    dim3 sm_grid(L_, B_ * H_);   // (2048, 64)
    softmax_kernel<<<sm_grid, 256>>>(attn_ptr);

    dim3 cx_grid(L_ / 64, B_ * H_);   // (32, 64)
    ctx_kernel<<<cx_grid, 256>>>(attn_ptr, Vbuf, Cbuf);

    gemm_bias_kernel<<<gemm_grid, 256>>>(Cbuf, Wo, bo, out, M_, D_, D_);
}

// round 3
// speedup vs baseline: 2.0246x; 2.0246x over previous
#include <cuda_runtime.h>
#include <cuda_bf16.h>
#include <cstdint>

// Problem constants
#define B_   4
#define L_   2048
#define D_   1024
#define H_   16
#define DK_  64
#define M_   (B_*L_)      // 8192

static const long long OUT_ELEMS  = (long long)B_ * L_ * D_;        // 8388608
static const long long ATTN_ELEMS = (long long)B_ * H_ * L_ * L_;   // 268435456

// Scratch (__device__ globals: allocation-free rule)
__device__ float g_Q[(size_t)M_ * D_];
__device__ float g_K[(size_t)M_ * D_];
__device__ float g_V[(size_t)M_ * D_];
__device__ float g_ctx[(size_t)M_ * D_];
__device__ float g_Wt[(size_t)4 * D_ * D_];           // transposed weights
__device__ float g_Vt[(size_t)B_ * D_ * L_];          // V transposed per (b): [D][L]
__device__ float g_attn[(size_t)B_ * H_ * L_ * L_];   // fallback attn

// ===========================================================================
// mma.sync helpers (PTX sm_80+, legal on the compute_103 base target)
// ===========================================================================
__device__ __forceinline__ void mma16816(float* d, const uint32_t* a, const uint32_t* b) {
    asm volatile(
        "mma.sync.aligned.m16n8k16.row.col.f32.bf16.bf16.f32 "
        "{%0,%1,%2,%3}, {%4,%5,%6,%7}, {%8,%9}, {%0,%1,%2,%3};"
        : "+f"(d[0]), "+f"(d[1]), "+f"(d[2]), "+f"(d[3])
        : "r"(a[0]), "r"(a[1]), "r"(a[2]), "r"(a[3]), "r"(b[0]), "r"(b[1]));
}

__device__ __forceinline__ uint32_t pack2(__nv_bfloat16 a, __nv_bfloat16 b) {
    return (uint32_t)__bfloat16_as_ushort(a) |
           ((uint32_t)__bfloat16_as_ushort(b) << 16);
}

// Load 8 consecutive fp32, split into hi/lo bf16 uint4 pairs
__device__ __forceinline__ void split8(const float* src, uint4& hi, uint4& lo) {
    float4 u = *(const float4*)src;
    float4 w = *(const float4*)(src + 4);
    float xs[8] = {u.x, u.y, u.z, u.w, w.x, w.y, w.z, w.w};
    __nv_bfloat16 h[8], l[8];
#pragma unroll
    for (int i = 0; i < 8; i++) {
        h[i] = __float2bfloat16(xs[i]);
        l[i] = __float2bfloat16(xs[i] - __bfloat162float(h[i]));
    }
    hi.x = pack2(h[0], h[1]); hi.y = pack2(h[2], h[3]);
    hi.z = pack2(h[4], h[5]); hi.w = pack2(h[6], h[7]);
    lo.x = pack2(l[0], l[1]); lo.y = pack2(l[2], l[3]);
    lo.z = pack2(l[4], l[5]); lo.w = pack2(l[6], l[7]);
}

struct GemmParams {
    const float* A; const float* B; const float* bias; float* C;
    long long lda, ldb, ldc;
    int k_chunks;      // K / 64
    float scale;
    int z_lo;          // z = zh*z_lo + zl
    long long a_hi, a_lo, b_hi, b_lo, c_hi, c_lo;
};

// ===========================================================================
// Unified tensor-core GEMM: C[m0:128, n0:NC] = scale*(A@B^T) + bias
// A: [M,K] fp32 rows stride lda (K-major).  B: [N,K] fp32 rows stride ldb.
// fp32 emulated as bf16 split: hi*hi + hi*lo + lo*hi  (3 passes).
// Smem tiles: [rows][72] bf16 (pitch 144B) -> conflict-free fragment LDS.
// ===========================================================================
#define KPITCH 72   // bf16 elements per smem row (64 data + 8 pad)

template<int NC>
__global__ void __launch_bounds__(256, 2)
mma_gemm(GemmParams p)
{
    constexpr int A_BYTES = 128 * KPITCH * 2;   // 18432
    constexpr int B_BYTES = NC * KPITCH * 2;
    constexpr int NF = NC / 16;                 // n-frags per warp (warp N = NC/2)

    extern __shared__ __align__(16) char sm[];
    char* sAhi = sm;
    char* sAlo = sm + A_BYTES;
    char* sBhi = sm + 2 * A_BYTES;
    char* sBlo = sm + 2 * A_BYTES + B_BYTES;

    int tid = threadIdx.x;
    int wid = tid >> 5, lane = tid & 31;

    int z = blockIdx.z;
    int zh = z / p.z_lo, zl = z % p.z_lo;
    const float* A  = p.A + (size_t)zh * p.a_hi + (size_t)zl * p.a_lo;
    const float* Bm = p.B + (size_t)zh * p.b_hi + (size_t)zl * p.b_lo;
    float* C = p.C + (size_t)zh * p.c_hi + (size_t)zl * p.c_lo;

    int m0 = blockIdx.y * 128;
    int n0 = blockIdx.x * NC;

    int warpM = (wid >> 1) * 32;        // 4 warp-rows
    int warpN = (wid & 1) * (NC / 2);   // 2 warp-cols

    float acc[2][NF][4];
#pragma unroll
    for (int i = 0; i < 2; i++)
#pragma unroll
        for (int j = 0; j < NF; j++)
#pragma unroll
            for (int r = 0; r < 4; r++) acc[i][j][r] = 0.f;

    for (int ck = 0; ck < p.k_chunks; ck++) {
        int k0 = ck * 64;
        // ---- load + split A tile: 128 rows x 64 k  (1024 groups of 8)
#pragma unroll
        for (int g = tid; g < 1024; g += 256) {
            int row = g >> 3, gc = (g & 7) * 8;
            uint4 hi, lo;
            split8(A + (size_t)(m0 + row) * p.lda + k0 + gc, hi, lo);
            int off = row * (KPITCH * 2) + gc * 2;
            *(uint4*)(sAhi + off) = hi;
            *(uint4*)(sAlo + off) = lo;
        }
        // ---- load + split B tile: NC rows x 64 k
#pragma unroll
        for (int g = tid; g < NC * 8; g += 256) {
            int row = g >> 3, gc = (g & 7) * 8;
            uint4 hi, lo;
            split8(Bm + (size_t)(n0 + row) * p.ldb + k0 + gc, hi, lo);
            int off = row * (KPITCH * 2) + gc * 2;
            *(uint4*)(sBhi + off) = hi;
            *(uint4*)(sBlo + off) = lo;
        }
        __syncthreads();

        int arow = warpM + (lane >> 2);
        int brow = warpN + (lane >> 2);
        int kq   = (lane & 3) * 2;

#pragma unroll
        for (int pass = 0; pass < 3; pass++) {
            const char* Ab = (pass == 2) ? sAlo : sAhi;
            const char* Bb = (pass == 1) ? sBlo : sBhi;
#pragma unroll
            for (int ks = 0; ks < 4; ks++) {
                int kk = ks * 16 + kq;
                uint32_t af[2][4];
#pragma unroll
                for (int mf = 0; mf < 2; mf++) {
                    int r = arow + mf * 16;
                    af[mf][0] = *(const uint32_t*)(Ab + (r     ) * (KPITCH*2) + kk * 2);
                    af[mf][1] = *(const uint32_t*)(Ab + (r + 8 ) * (KPITCH*2) + kk * 2);
                    af[mf][2] = *(const uint32_t*)(Ab + (r     ) * (KPITCH*2) + (kk + 8) * 2);
                    af[mf][3] = *(const uint32_t*)(Ab + (r + 8 ) * (KPITCH*2) + (kk + 8) * 2);
                }
                uint32_t bf[NF][2];
#pragma unroll
                for (int nf = 0; nf < NF; nf++) {
                    int n = brow + nf * 8;
                    bf[nf][0] = *(const uint32_t*)(Bb + n * (KPITCH*2) + kk * 2);
                    bf[nf][1] = *(const uint32_t*)(Bb + n * (KPITCH*2) + (kk + 8) * 2);
                }
#pragma unroll
                for (int mf = 0; mf < 2; mf++)
#pragma unroll
                    for (int nf = 0; nf < NF; nf++)
                        mma16816(acc[mf][nf], af[mf], bf[nf]);
            }
        }
        __syncthreads();
    }

    // ---- Epilogue: direct STG (each frag row = full 32B sector from 4 lanes)
#pragma unroll
    for (int nf = 0; nf < NF; nf++) {
        int col = n0 + warpN + nf * 8 + (lane & 3) * 2;
        float b0 = 0.f, b1 = 0.f;
        if (p.bias) {
            float2 bb = *(const float2*)(p.bias + col);
            b0 = bb.x; b1 = bb.y;
        }
#pragma unroll
        for (int mf = 0; mf < 2; mf++) {
            int r = m0 + warpM + mf * 16 + (lane >> 2);
            float2 v0, v1;
            v0.x = acc[mf][nf][0] * p.scale + b0;
            v0.y = acc[mf][nf][1] * p.scale + b1;
            v1.x = acc[mf][nf][2] * p.scale + b0;
            v1.y = acc[mf][nf][3] * p.scale + b1;
            *(float2*)(C + (size_t)r * p.ldc + col) = v0;
            *(float2*)(C + (size_t)(r + 8) * p.ldc + col) = v1;
        }
    }
}

// ===========================================================================
// Batched 32x32 tiled transpose: dst[z][c][r] = src[z][r][c]
// ===========================================================================
__global__ void __launch_bounds__(256)
transpose_kernel(const float* __restrict__ src, float* __restrict__ dst,
                 int R, int C, long long sb, long long db)
{
    __shared__ float t[32][33];
    int z = blockIdx.z;
    const float* s = src + (size_t)z * sb;
    float* d = dst + (size_t)z * db;
    int c0 = blockIdx.x * 32, r0 = blockIdx.y * 32;
    int tx = threadIdx.x & 31, ty = threadIdx.x >> 5;
#pragma unroll
    for (int i = ty; i < 32; i += 8)
        t[i][tx] = s[(size_t)(r0 + i) * C + c0 + tx];
    __syncthreads();
#pragma unroll
    for (int i = ty; i < 32; i += 8)
        d[(size_t)(c0 + i) * R + r0 + tx] = t[tx][i];
}

// ===========================================================================
// In-place row softmax over last dim (2048). One block (256 thr) per row.
// ===========================================================================
__global__ void __launch_bounds__(256) softmax_kernel(float* __restrict__ attn)
{
    __shared__ float red_max[8];
    __shared__ float red_sum[8];
    size_t row = (size_t)blockIdx.y * (size_t)gridDim.x + blockIdx.x;
    float* p = attn + row * (size_t)L_;
    int tid = threadIdx.x;

    float4 a = *(float4*)(p + tid * 8);
    float4 b = *(float4*)(p + tid * 8 + 4);

    float m = fmaxf(fmaxf(fmaxf(a.x, a.y), fmaxf(a.z, a.w)),
                    fmaxf(fmaxf(b.x, b.y), fmaxf(b.z, b.w)));
#pragma unroll
    for (int o = 16; o > 0; o >>= 1)
        m = fmaxf(m, __shfl_xor_sync(0xFFFFFFFFu, m, o));
    if ((tid & 31) == 0) red_max[tid >> 5] = m;
    __syncthreads();
    float mall = red_max[0];
#pragma unroll
    for (int i = 1; i < 8; i++) mall = fmaxf(mall, red_max[i]);

    a.x = __expf(a.x - mall); a.y = __expf(a.y - mall);
    a.z = __expf(a.z - mall); a.w = __expf(a.w - mall);
    b.x = __expf(b.x - mall); b.y = __expf(b.y - mall);
    b.z = __expf(b.z - mall); b.w = __expf(b.w - mall);

    float s = a.x + a.y + a.z + a.w + b.x + b.y + b.z + b.w;
#pragma unroll
    for (int o = 16; o > 0; o >>= 1)
        s += __shfl_xor_sync(0xFFFFFFFFu, s, o);
    if ((tid & 31) == 0) red_sum[tid >> 5] = s;
    __syncthreads();
    float sall = 0.f;
#pragma unroll
    for (int i = 0; i < 8; i++) sall += red_sum[i];

    float inv = 1.0f / sall;
    a.x *= inv; a.y *= inv; a.z *= inv; a.w *= inv;
    b.x *= inv; b.y *= inv; b.z *= inv; b.w *= inv;
    *(float4*)(p + tid * 8) = a;
    *(float4*)(p + tid * 8 + 4) = b;
}

// ===========================================================================
extern "C" void kernel_launch(void* const* d_in, const int* in_sizes, int n_in,
                              void* d_out, int out_size)
{
    const float* query = (const float*)d_in[0];
    const float* key_  = (const float*)d_in[1];
    const float* value = (const float*)d_in[2];
    const float* Wq    = (const float*)d_in[3];
    const float* bq    = (const float*)d_in[4];
    const float* Wk    = (const float*)d_in[5];
    const float* bk    = (const float*)d_in[6];
    const float* Wv    = (const float*)d_in[7];
    const float* bv    = (const float*)d_in[8];
    const float* Wo    = (const float*)d_in[9];
    const float* bo    = (const float*)d_in[10];

    float* out = (float*)d_out;

    float* attn_ptr = nullptr;
    if ((long long)out_size >= OUT_ELEMS + ATTN_ELEMS) {
        attn_ptr = out + OUT_ELEMS;
    } else {
        cudaGetSymbolAddress((void**)&attn_ptr, g_attn);
    }

    float* Qbuf; cudaGetSymbolAddress((void**)&Qbuf, g_Q);
    float* Kbuf; cudaGetSymbolAddress((void**)&Kbuf, g_K);
    float* Vbuf; cudaGetSymbolAddress((void**)&Vbuf, g_V);
    float* Cbuf; cudaGetSymbolAddress((void**)&Cbuf, g_ctx);
    float* Wt;   cudaGetSymbolAddress((void**)&Wt,   g_Wt);
    float* Vt;   cudaGetSymbolAddress((void**)&Vt,   g_Vt);

    const int SMEM128 = 2 * (128 * KPITCH * 2) + 2 * (128 * KPITCH * 2);  // 73728
    const int SMEM64  = 2 * (128 * KPITCH * 2) + 2 * (64 * KPITCH * 2);   // 55296
    cudaFuncSetAttribute(mma_gemm<128>, cudaFuncAttributeMaxDynamicSharedMemorySize, SMEM128);
    cudaFuncSetAttribute(mma_gemm<64>,  cudaFuncAttributeMaxDynamicSharedMemorySize, SMEM64);

    // 1. Transpose weights: Wt[i][n][k] = W[k][n]
    const float* Ws[4] = {Wq, Wk, Wv, Wo};
    for (int i = 0; i < 4; i++)
        transpose_kernel<<<dim3(32, 32, 1), 256>>>(
            Ws[i], Wt + (size_t)i * D_ * D_, D_, D_, 0, 0);

    // 2. Projections: [8192,1024] = X @ W + b
    GemmParams pp{};
    pp.lda = D_; pp.ldb = D_; pp.ldc = D_;
    pp.k_chunks = D_ / 64; pp.scale = 1.0f;
    pp.z_lo = 1;
    pp.a_hi = pp.a_lo = pp.b_hi = pp.b_lo = pp.c_hi = pp.c_lo = 0;

    dim3 pgrid(D_ / 128, M_ / 128, 1);   // (8, 64)
    GemmParams pq = pp; pq.A = query; pq.B = Wt + 0 * (size_t)D_ * D_; pq.bias = bq; pq.C = Qbuf;
    mma_gemm<128><<<pgrid, 256, SMEM128>>>(pq);
    GemmParams pk = pp; pk.A = key_;  pk.B = Wt + 1 * (size_t)D_ * D_; pk.bias = bk; pk.C = Kbuf;
    mma_gemm<128><<<pgrid, 256, SMEM128>>>(pk);
    GemmParams pv = pp; pv.A = value; pv.B = Wt + 2 * (size_t)D_ * D_; pv.bias = bv; pv.C = Vbuf;
    mma_gemm<128><<<pgrid, 256, SMEM128>>>(pv);

    // 3. V transpose per batch: Vt[b][d][l] = V[b][l][d]
    transpose_kernel<<<dim3(D_ / 32, L_ / 32, B_), 256>>>(
        Vbuf, Vt, L_, D_, (long long)L_ * D_, (long long)D_ * L_);

    // 4. Scores: attn[bh] = 0.125 * Q_h @ K_h^T   (z = bh, K=64 single chunk)
    GemmParams ps{};
    ps.A = Qbuf; ps.B = Kbuf; ps.bias = nullptr; ps.C = attn_ptr;
    ps.lda = D_; ps.ldb = D_; ps.ldc = L_;
    ps.k_chunks = 1; ps.scale = 0.125f;
    ps.z_lo = H_;
    ps.a_hi = (long long)L_ * D_; ps.a_lo = DK_;
    ps.b_hi = (long long)L_ * D_; ps.b_lo = DK_;
    ps.c_hi = (long long)H_ * L_ * L_; ps.c_lo = (long long)L_ * L_;
    mma_gemm<128><<<dim3(L_ / 128, L_ / 128, B_ * H_), 256, SMEM128>>>(ps);

    // 5. Softmax (in place)
    softmax_kernel<<<dim3(L_, B_ * H_), 256>>>(attn_ptr);

    // 6. ctx[b,l,h*64+d] = attn[bh] @ Vt[bh]^T   (N=64, K=2048)
    GemmParams pc{};
    pc.A = attn_ptr; pc.B = Vt; pc.bias = nullptr; pc.C = Cbuf;
    pc.lda = L_; pc.ldb = L_; pc.ldc = D_;
    pc.k_chunks = L_ / 64; pc.scale = 1.0f;
    pc.z_lo = H_;
    pc.a_hi = (long long)H_ * L_ * L_; pc.a_lo = (long long)L_ * L_;
    pc.b_hi = (long long)D_ * L_;      pc.b_lo = (long long)DK_ * L_;
    pc.c_hi = (long long)L_ * D_;      pc.c_lo = DK_;
    mma_gemm<64><<<dim3(1, L_ / 128, B_ * H_), 256, SMEM64>>>(pc);

    // 7. out = ctx @ Wo + bo
    GemmParams po = pp; po.A = Cbuf; po.B = Wt + 3 * (size_t)D_ * D_; po.bias = bo; po.C = out;
    mma_gemm<128><<<pgrid, 256, SMEM128>>>(po);
}

// round 6
// speedup vs baseline: 2.2946x; 1.1333x over previous
#include <cuda_runtime.h>
#include <cuda_bf16.h>
#include <cstdint>

// Problem constants
#define B_   4
#define L_   2048
#define D_   1024
#define H_   16
#define DK_  64
#define M_   (B_*L_)      // 8192

static const long long OUT_ELEMS  = (long long)B_ * L_ * D_;        // 8388608
static const long long ATTN_ELEMS = (long long)B_ * H_ * L_ * L_;   // 268435456

// Scratch (__device__ globals: allocation-free rule)
__device__ float g_Q[(size_t)M_ * D_];
__device__ float g_K[(size_t)M_ * D_];
__device__ float g_V[(size_t)M_ * D_];
__device__ float g_ctx[(size_t)M_ * D_];
__device__ float g_Wt[(size_t)4 * D_ * D_];           // transposed weights
__device__ float g_Vt[(size_t)B_ * D_ * L_];          // V transposed per (b): [D][L]
__device__ float g_attn[(size_t)B_ * H_ * L_ * L_];   // fallback attn (fp32 or bf16 view)

// ===========================================================================
// mma.sync helpers (PTX sm_80+, legal on the compute_103 base target)
// ===========================================================================
__device__ __forceinline__ void mma16816(float* d, const uint32_t* a, const uint32_t* b) {
    asm volatile(
        "mma.sync.aligned.m16n8k16.row.col.f32.bf16.bf16.f32 "
        "{%0,%1,%2,%3}, {%4,%5,%6,%7}, {%8,%9}, {%0,%1,%2,%3};"
        : "+f"(d[0]), "+f"(d[1]), "+f"(d[2]), "+f"(d[3])
        : "r"(a[0]), "r"(a[1]), "r"(a[2]), "r"(a[3]), "r"(b[0]), "r"(b[1]));
}

__device__ __forceinline__ uint32_t pack2f(float lo, float hi) {
    uint32_t r;
    asm("cvt.rn.bf16x2.f32 %0, %1, %2;" : "=r"(r) : "f"(hi), "f"(lo));
    return r;
}

// Load 8 consecutive fp32, split into hi/lo bf16 uint4 pairs.
// hi pair packed with cvt.rn.bf16x2; hi-as-f32 recovered exactly via shifts.
__device__ __forceinline__ void split8(const float* src, uint4& hi, uint4& lo) {
    float4 u = *(const float4*)src;
    float4 w = *(const float4*)(src + 4);
    float xs[8] = {u.x, u.y, u.z, u.w, w.x, w.y, w.z, w.w};
    uint32_t h[4], l[4];
#pragma unroll
    for (int i = 0; i < 4; i++) {
        uint32_t hp = pack2f(xs[2*i], xs[2*i+1]);
        float h0 = __uint_as_float(hp << 16);
        float h1 = __uint_as_float(hp & 0xFFFF0000u);
        l[i] = pack2f(xs[2*i] - h0, xs[2*i+1] - h1);
        h[i] = hp;
    }
    hi.x = h[0]; hi.y = h[1]; hi.z = h[2]; hi.w = h[3];
    lo.x = l[0]; lo.y = l[1]; lo.z = l[2]; lo.w = l[3];
}

struct GemmParams {
    const void* A; const float* B; const float* bias; void* C;
    long long lda, ldb, ldc;
    int k_chunks;      // K / 64
    float scale;
    int z_lo;          // z = zh*z_lo + zl
    long long a_hi, a_lo, b_hi, b_lo, c_hi, c_lo;
};

// ===========================================================================
// Unified tensor-core GEMM: C[m0:128, n0:NC] = scale*(A@B^T) + bias
// AMODE 0: A fp32 [M,K] -> hi/lo split, 3 MMA passes (hh, hl, lh)
// AMODE 1: A bf16 [M,K] -> direct copy, 2 MMA passes (hh, hl) (A_lo == 0)
// OBF16 0: C fp32;  OBF16 1: C bf16
// Smem tiles: [rows][72] bf16 (pitch 144B) -> conflict-free fragment LDS.
// ===========================================================================
#define KPITCH 72   // bf16 elements per smem row (64 data + 8 pad)

template<int NC, int AMODE, int OBF16>
__global__ void __launch_bounds__(256, 2)
mma_gemm(GemmParams p)
{
    constexpr int A_BYTES = 128 * KPITCH * 2;   // 18432
    constexpr int B_BYTES = NC * KPITCH * 2;
    constexpr int NF = NC / 16;                 // n-frags per warp (warp N = NC/2)
    constexpr int NPASS = AMODE ? 2 : 3;
    constexpr int NABUF = AMODE ? 1 : 2;

    extern __shared__ __align__(16) char sm[];
    char* sAhi = sm;
    char* sAlo = sm + A_BYTES;                  // unused when AMODE==1
    char* sBhi = sm + NABUF * A_BYTES;
    char* sBlo = sBhi + B_BYTES;

    int tid = threadIdx.x;
    int wid = tid >> 5, lane = tid & 31;

    int z = blockIdx.z;
    int zh = z / p.z_lo, zl = z % p.z_lo;
    const float* Bm = p.B + (size_t)zh * p.b_hi + (size_t)zl * p.b_lo;

    int m0 = blockIdx.y * 128;
    int n0 = blockIdx.x * NC;

    int warpM = (wid >> 1) * 32;        // 4 warp-rows
    int warpN = (wid & 1) * (NC / 2);   // 2 warp-cols

    float acc[2][NF][4];
#pragma unroll
    for (int i = 0; i < 2; i++)
#pragma unroll
        for (int j = 0; j < NF; j++)
#pragma unroll
            for (int r = 0; r < 4; r++) acc[i][j][r] = 0.f;

    for (int ck = 0; ck < p.k_chunks; ck++) {
        int k0 = ck * 64;
        // ---- A tile: 128 rows x 64 k
        if (AMODE == 0) {
            const float* A = (const float*)p.A + (size_t)zh * p.a_hi + (size_t)zl * p.a_lo;
#pragma unroll
            for (int g = tid; g < 1024; g += 256) {
                int row = g >> 3, gc = (g & 7) * 8;
                uint4 hi, lo;
                split8(A + (size_t)(m0 + row) * p.lda + k0 + gc, hi, lo);
                int off = row * (KPITCH * 2) + gc * 2;
                *(uint4*)(sAhi + off) = hi;
                *(uint4*)(sAlo + off) = lo;
            }
        } else {
            const __nv_bfloat16* A = (const __nv_bfloat16*)p.A +
                (size_t)zh * p.a_hi + (size_t)zl * p.a_lo;
#pragma unroll
            for (int g = tid; g < 1024; g += 256) {
                int row = g >> 3, seg = (g & 7);
                uint4 v = *(const uint4*)(A + (size_t)(m0 + row) * p.lda + k0 + seg * 8);
                *(uint4*)(sAhi + row * (KPITCH * 2) + seg * 16) = v;
            }
        }
        // ---- B tile: NC rows x 64 k (fp32, split)
#pragma unroll
        for (int g = tid; g < NC * 8; g += 256) {
            int row = g >> 3, gc = (g & 7) * 8;
            uint4 hi, lo;
            split8(Bm + (size_t)(n0 + row) * p.ldb + k0 + gc, hi, lo);
            int off = row * (KPITCH * 2) + gc * 2;
            *(uint4*)(sBhi + off) = hi;
            *(uint4*)(sBlo + off) = lo;
        }
        __syncthreads();

        int arow = warpM + (lane >> 2);
        int brow = warpN + (lane >> 2);
        int kq   = (lane & 3) * 2;

#pragma unroll
        for (int pass = 0; pass < NPASS; pass++) {
            const char* Ab = (pass == 2) ? sAlo : sAhi;
            const char* Bb = (pass == 1) ? sBlo : sBhi;
#pragma unroll
            for (int ks = 0; ks < 4; ks++) {
                int kk = ks * 16 + kq;
                uint32_t af[2][4];
#pragma unroll
                for (int mf = 0; mf < 2; mf++) {
                    int r = arow + mf * 16;
                    af[mf][0] = *(const uint32_t*)(Ab + (r     ) * (KPITCH*2) + kk * 2);
                    af[mf][1] = *(const uint32_t*)(Ab + (r + 8 ) * (KPITCH*2) + kk * 2);
                    af[mf][2] = *(const uint32_t*)(Ab + (r     ) * (KPITCH*2) + (kk + 8) * 2);
                    af[mf][3] = *(const uint32_t*)(Ab + (r + 8 ) * (KPITCH*2) + (kk + 8) * 2);
                }
                uint32_t bfr[NF][2];
#pragma unroll
                for (int nf = 0; nf < NF; nf++) {
                    int n = brow + nf * 8;
                    bfr[nf][0] = *(const uint32_t*)(Bb + n * (KPITCH*2) + kk * 2);
                    bfr[nf][1] = *(const uint32_t*)(Bb + n * (KPITCH*2) + (kk + 8) * 2);
                }
#pragma unroll
                for (int mf = 0; mf < 2; mf++)
#pragma unroll
                    for (int nf = 0; nf < NF; nf++)
                        mma16816(acc[mf][nf], af[mf], bfr[nf]);
            }
        }
        __syncthreads();
    }

    // ---- Epilogue: direct STG
#pragma unroll
    for (int nf = 0; nf < NF; nf++) {
        int col = n0 + warpN + nf * 8 + (lane & 3) * 2;
        float b0 = 0.f, b1 = 0.f;
        if (p.bias) {
            float2 bb = *(const float2*)(p.bias + col);
            b0 = bb.x; b1 = bb.y;
        }
#pragma unroll
        for (int mf = 0; mf < 2; mf++) {
            int r = m0 + warpM + mf * 16 + (lane >> 2);
            float v00 = acc[mf][nf][0] * p.scale + b0;
            float v01 = acc[mf][nf][1] * p.scale + b1;
            float v10 = acc[mf][nf][2] * p.scale + b0;
            float v11 = acc[mf][nf][3] * p.scale + b1;
            if (OBF16 == 0) {
                float* C = (float*)p.C + (size_t)zh * p.c_hi + (size_t)zl * p.c_lo;
                *(float2*)(C + (size_t)r * p.ldc + col) = make_float2(v00, v01);
                *(float2*)(C + (size_t)(r + 8) * p.ldc + col) = make_float2(v10, v11);
            } else {
                __nv_bfloat16* C = (__nv_bfloat16*)p.C + (size_t)zh * p.c_hi + (size_t)zl * p.c_lo;
                *(uint32_t*)(C + (size_t)r * p.ldc + col) = pack2f(v00, v01);
                *(uint32_t*)(C + (size_t)(r + 8) * p.ldc + col) = pack2f(v10, v11);
            }
        }
    }
}

// ===========================================================================
// Batched 32x32 tiled transpose: dst[z][c][r] = src[z][r][c]
// ===========================================================================
__global__ void __launch_bounds__(256)
transpose_kernel(const float* __restrict__ src, float* __restrict__ dst,
                 int R, int C, long long sb, long long db)
{
    __shared__ float t[32][33];
    int z = blockIdx.z;
    const float* s = src + (size_t)z * sb;
    float* d = dst + (size_t)z * db;
    int c0 = blockIdx.x * 32, r0 = blockIdx.y * 32;
    int tx = threadIdx.x & 31, ty = threadIdx.x >> 5;
#pragma unroll
    for (int i = ty; i < 32; i += 8)
        t[i][tx] = s[(size_t)(r0 + i) * C + c0 + tx];
    __syncthreads();
#pragma unroll
    for (int i = ty; i < 32; i += 8)
        d[(size_t)(c0 + i) * R + r0 + tx] = t[tx][i];
}

// ===========================================================================
// Softmax kernels: one block (256 thr) per 2048-wide row.
// ===========================================================================
__device__ __forceinline__ float block_reduce(float v, bool is_max,
                                              float* red, int tid)
{
#pragma unroll
    for (int o = 16; o > 0; o >>= 1) {
        float t = __shfl_xor_sync(0xFFFFFFFFu, v, o);
        v = is_max ? fmaxf(v, t) : v + t;
    }
    if ((tid & 31) == 0) red[tid >> 5] = v;
    __syncthreads();
    float r = red[0];
#pragma unroll
    for (int i = 1; i < 8; i++) r = is_max ? fmaxf(r, red[i]) : r + red[i];
    return r;
}

__global__ void __launch_bounds__(256) softmax_kernel(float* __restrict__ attn)
{
    __shared__ float red[8];
    size_t row = (size_t)blockIdx.y * (size_t)gridDim.x + blockIdx.x;
    float* p = attn + row * (size_t)L_;
    int tid = threadIdx.x;

    float4 a = *(float4*)(p + tid * 8);
    float4 b = *(float4*)(p + tid * 8 + 4);

    float m = fmaxf(fmaxf(fmaxf(a.x, a.y), fmaxf(a.z, a.w)),
                    fmaxf(fmaxf(b.x, b.y), fmaxf(b.z, b.w)));
    float mall = block_reduce(m, true, red, tid);
    __syncthreads();

    a.x = __expf(a.x - mall); a.y = __expf(a.y - mall);
    a.z = __expf(a.z - mall); a.w = __expf(a.w - mall);
    b.x = __expf(b.x - mall); b.y = __expf(b.y - mall);
    b.z = __expf(b.z - mall); b.w = __expf(b.w - mall);

    float s = a.x + a.y + a.z + a.w + b.x + b.y + b.z + b.w;
    float sall = block_reduce(s, false, red, tid);

    float inv = 1.0f / sall;
    a.x *= inv; a.y *= inv; a.z *= inv; a.w *= inv;
    b.x *= inv; b.y *= inv; b.z *= inv; b.w *= inv;
    *(float4*)(p + tid * 8) = a;
    *(float4*)(p + tid * 8 + 4) = b;
}

__global__ void __launch_bounds__(256) softmax_bf16_kernel(__nv_bfloat16* __restrict__ attn)
{
    __shared__ float red[8];
    size_t row = (size_t)blockIdx.y * (size_t)gridDim.x + blockIdx.x;
    __nv_bfloat16* p = attn + row * (size_t)L_;
    int tid = threadIdx.x;

    uint4 raw = *(uint4*)(p + tid * 8);
    uint32_t w[4] = {raw.x, raw.y, raw.z, raw.w};
    float x[8];
#pragma unroll
    for (int i = 0; i < 4; i++) {
        x[2*i]   = __uint_as_float(w[i] << 16);
        x[2*i+1] = __uint_as_float(w[i] & 0xFFFF0000u);
    }

    float m = x[0];
#pragma unroll
    for (int i = 1; i < 8; i++) m = fmaxf(m, x[i]);
    float mall = block_reduce(m, true, red, tid);
    __syncthreads();

    float s = 0.f;
#pragma unroll
    for (int i = 0; i < 8; i++) { x[i] = __expf(x[i] - mall); s += x[i]; }
    float sall = block_reduce(s, false, red, tid);

    float inv = 1.0f / sall;
#pragma unroll
    for (int i = 0; i < 4; i++)
        w[i] = pack2f(x[2*i] * inv, x[2*i+1] * inv);
    *(uint4*)(p + tid * 8) = make_uint4(w[0], w[1], w[2], w[3]);
}

// ===========================================================================
extern "C" void kernel_launch(void* const* d_in, const int* in_sizes, int n_in,
                              void* d_out, int out_size)
{
    const float* query = (const float*)d_in[0];
    const float* key_  = (const float*)d_in[1];
    const float* value = (const float*)d_in[2];
    const float* Wq    = (const float*)d_in[3];
    const float* bq    = (const float*)d_in[4];
    const float* Wk    = (const float*)d_in[5];
    const float* bk    = (const float*)d_in[6];
    const float* Wv    = (const float*)d_in[7];
    const float* bv    = (const float*)d_in[8];
    const float* Wo    = (const float*)d_in[9];
    const float* bo    = (const float*)d_in[10];

    float* out = (float*)d_out;
    bool attn_in_out = ((long long)out_size >= OUT_ELEMS + ATTN_ELEMS);

    float* attn_f32 = nullptr;
    if (attn_in_out) attn_f32 = out + OUT_ELEMS;
    else cudaGetSymbolAddress((void**)&attn_f32, g_attn);
    __nv_bfloat16* attn_b16 = (__nv_bfloat16*)attn_f32;   // bf16 view (small path)

    float* Qbuf; cudaGetSymbolAddress((void**)&Qbuf, g_Q);
    float* Kbuf; cudaGetSymbolAddress((void**)&Kbuf, g_K);
    float* Vbuf; cudaGetSymbolAddress((void**)&Vbuf, g_V);
    float* Cbuf; cudaGetSymbolAddress((void**)&Cbuf, g_ctx);
    float* Wt;   cudaGetSymbolAddress((void**)&Wt,   g_Wt);
    float* Vt;   cudaGetSymbolAddress((void**)&Vt,   g_Vt);

    const int SMEM_P   = 4 * (128 * KPITCH * 2);                       // 73728 (proj/out/scores)
    const int SMEM_C3  = 2*(128*KPITCH*2) + 2*(64*KPITCH*2);           // 55296 (ctx fp32)
    const int SMEM_C2  = 1*(128*KPITCH*2) + 2*(64*KPITCH*2);           // 36864 (ctx bf16)
    cudaFuncSetAttribute(mma_gemm<128,0,0>, cudaFuncAttributeMaxDynamicSharedMemorySize, SMEM_P);
    cudaFuncSetAttribute(mma_gemm<128,0,1>, cudaFuncAttributeMaxDynamicSharedMemorySize, SMEM_P);
    cudaFuncSetAttribute(mma_gemm<64,0,0>,  cudaFuncAttributeMaxDynamicSharedMemorySize, SMEM_C3);
    cudaFuncSetAttribute(mma_gemm<64,1,0>,  cudaFuncAttributeMaxDynamicSharedMemorySize, SMEM_C2);

    // 1. Transpose weights: Wt[i][n][k] = W[k][n]
    const float* Ws[4] = {Wq, Wk, Wv, Wo};
    for (int i = 0; i < 4; i++)
        transpose_kernel<<<dim3(32, 32, 1), 256>>>(
            Ws[i], Wt + (size_t)i * D_ * D_, D_, D_, 0, 0);

    // 2. Projections: [8192,1024] = X @ W + b
    GemmParams pp{};
    pp.lda = D_; pp.ldb = D_; pp.ldc = D_;
    pp.k_chunks = D_ / 64; pp.scale = 1.0f;
    pp.z_lo = 1;
    pp.a_hi = pp.a_lo = pp.b_hi = pp.b_lo = pp.c_hi = pp.c_lo = 0;

    dim3 pgrid(D_ / 128, M_ / 128, 1);   // (8, 64)
    GemmParams pq = pp; pq.A = query; pq.B = Wt + 0 * (size_t)D_ * D_; pq.bias = bq; pq.C = Qbuf;
    mma_gemm<128,0,0><<<pgrid, 256, SMEM_P>>>(pq);
    GemmParams pk = pp; pk.A = key_;  pk.B = Wt + 1 * (size_t)D_ * D_; pk.bias = bk; pk.C = Kbuf;
    mma_gemm<128,0,0><<<pgrid, 256, SMEM_P>>>(pk);
    GemmParams pv = pp; pv.A = value; pv.B = Wt + 2 * (size_t)D_ * D_; pv.bias = bv; pv.C = Vbuf;
    mma_gemm<128,0,0><<<pgrid, 256, SMEM_P>>>(pv);

    // 3. V transpose per batch: Vt[b][d][l] = V[b][l][d]
    transpose_kernel<<<dim3(D_ / 32, L_ / 32, B_), 256>>>(
        Vbuf, Vt, L_, D_, (long long)L_ * D_, (long long)D_ * L_);

    // 4. Scores: attn[bh] = 0.125 * Q_h @ K_h^T   (z = bh, K=64 single chunk)
    GemmParams ps{};
    ps.A = Qbuf; ps.B = Kbuf; ps.bias = nullptr;
    ps.lda = D_; ps.ldb = D_; ps.ldc = L_;
    ps.k_chunks = 1; ps.scale = 0.125f;
    ps.z_lo = H_;
    ps.a_hi = (long long)L_ * D_; ps.a_lo = DK_;
    ps.b_hi = (long long)L_ * D_; ps.b_lo = DK_;
    ps.c_hi = (long long)H_ * L_ * L_; ps.c_lo = (long long)L_ * L_;
    dim3 sgrid(L_ / 128, L_ / 128, B_ * H_);

    // 6. ctx[b,l,h*64+d] = attn[bh] @ Vt[bh]^T   (N=64, K=2048)
    GemmParams pc{};
    pc.B = Vt; pc.bias = nullptr; pc.C = Cbuf;
    pc.lda = L_; pc.ldb = L_; pc.ldc = D_;
    pc.k_chunks = L_ / 64; pc.scale = 1.0f;
    pc.z_lo = H_;
    pc.a_hi = (long long)H_ * L_ * L_; pc.a_lo = (long long)L_ * L_;
    pc.b_hi = (long long)D_ * L_;      pc.b_lo = (long long)DK_ * L_;
    pc.c_hi = (long long)L_ * D_;      pc.c_lo = DK_;
    dim3 cgrid(1, L_ / 128, B_ * H_);

    if (attn_in_out) {
        ps.C = attn_f32;
        mma_gemm<128,0,0><<<sgrid, 256, SMEM_P>>>(ps);
        softmax_kernel<<<dim3(L_, B_ * H_), 256>>>(attn_f32);
        pc.A = attn_f32;
        mma_gemm<64,0,0><<<cgrid, 256, SMEM_C3>>>(pc);
    } else {
        ps.C = attn_b16;
        mma_gemm<128,0,1><<<sgrid, 256, SMEM_P>>>(ps);
        softmax_bf16_kernel<<<dim3(L_, B_ * H_), 256>>>(attn_b16);
        pc.A = attn_b16;
        mma_gemm<64,1,0><<<cgrid, 256, SMEM_C2>>>(pc);
    }

    // 7. out = ctx @ Wo + bo
    GemmParams po = pp; po.A = Cbuf; po.B = Wt + 3 * (size_t)D_ * D_; po.bias = bo; po.C = out;
    mma_gemm<128,0,0><<<pgrid, 256, SMEM_P>>>(po);
}